// round 2
// baseline (speedup 1.0000x reference)
#include <cuda_runtime.h>
#include <cuda_bf16.h>

// y = 0.75 * x @ colsum(W)
// x: [M,K] fp32 row-major, W: [N,K] fp32 row-major, out: [M,1] fp32
// M = K = N = 8192.

#define M_DIM 8192
#define K_DIM 8192
#define N_DIM 8192

// Scratch: column sums of W. __device__ global (no allocations allowed).
__device__ float g_wcs[K_DIM];

// ---------------------------------------------------------------------------
// Kernel 0: zero the scratch (graph replays call kernel_launch repeatedly;
// must be deterministic each call).
// ---------------------------------------------------------------------------
__global__ void zero_wcs_kernel() {
    int i = blockIdx.x * blockDim.x + threadIdx.x;
    if (i < K_DIM) g_wcs[i] = 0.0f;
}

// ---------------------------------------------------------------------------
// Kernel 1: column-sum of W.
// Grid: (K/4/256, ROW_SPLITS). Each thread owns one float4 column group and
// accumulates ROWS_PER_SPLIT rows with 4 independent accumulators
// (structural MLP >= 4), then 4 atomicAdds into g_wcs.
// ---------------------------------------------------------------------------
#define CS_THREADS 256
#define ROW_SPLITS 128
#define ROWS_PER_SPLIT (N_DIM / ROW_SPLITS)   // 64

__global__ __launch_bounds__(CS_THREADS)
void colsum_kernel(const float* __restrict__ W) {
    const int col4 = blockIdx.x * CS_THREADS + threadIdx.x;  // float4 index
    const int r0 = blockIdx.y * ROWS_PER_SPLIT;
    const float4* __restrict__ Wv = reinterpret_cast<const float4*>(W);
    const long long ld4 = K_DIM / 4;

    float4 a0 = make_float4(0.f, 0.f, 0.f, 0.f);
    float4 a1 = make_float4(0.f, 0.f, 0.f, 0.f);
    float4 a2 = make_float4(0.f, 0.f, 0.f, 0.f);
    float4 a3 = make_float4(0.f, 0.f, 0.f, 0.f);

#pragma unroll 4
    for (int r = 0; r < ROWS_PER_SPLIT; r += 4) {
        float4 v0 = Wv[(long long)(r0 + r + 0) * ld4 + col4];
        float4 v1 = Wv[(long long)(r0 + r + 1) * ld4 + col4];
        float4 v2 = Wv[(long long)(r0 + r + 2) * ld4 + col4];
        float4 v3 = Wv[(long long)(r0 + r + 3) * ld4 + col4];
        a0.x += v0.x; a0.y += v0.y; a0.z += v0.z; a0.w += v0.w;
        a1.x += v1.x; a1.y += v1.y; a1.z += v1.z; a1.w += v1.w;
        a2.x += v2.x; a2.y += v2.y; a2.z += v2.z; a2.w += v2.w;
        a3.x += v3.x; a3.y += v3.y; a3.z += v3.z; a3.w += v3.w;
    }

    float4 acc;
    acc.x = (a0.x + a1.x) + (a2.x + a3.x);
    acc.y = (a0.y + a1.y) + (a2.y + a3.y);
    acc.z = (a0.z + a1.z) + (a2.z + a3.z);
    acc.w = (a0.w + a1.w) + (a2.w + a3.w);

    float* dst = &g_wcs[col4 * 4];
    atomicAdd(dst + 0, acc.x);
    atomicAdd(dst + 1, acc.y);
    atomicAdd(dst + 2, acc.z);
    atomicAdd(dst + 3, acc.w);
}

// ---------------------------------------------------------------------------
// Kernel 2: per-row dot product against g_wcs (32 KB, L2-resident).
// ROWS_PER_BLOCK rows per block; float4 loads; warp shuffle + smem reduce.
// ---------------------------------------------------------------------------
#define RD_THREADS 256
#define ROWS_PER_BLOCK 2

__global__ __launch_bounds__(RD_THREADS)
void rowdot_kernel(const float* __restrict__ x, float* __restrict__ y) {
    const float4* __restrict__ wv = reinterpret_cast<const float4*>(g_wcs);
    __shared__ float warp_sums[ROWS_PER_BLOCK][RD_THREADS / 32];

    const int m0 = blockIdx.x * ROWS_PER_BLOCK;

#pragma unroll
    for (int rr = 0; rr < ROWS_PER_BLOCK; ++rr) {
        const int m = m0 + rr;
        const float4* __restrict__ xv =
            reinterpret_cast<const float4*>(x + (long long)m * K_DIM);

        float acc = 0.0f;
        // K/4 = 2048 float4 per row; 256 threads -> 8 independent loads each.
#pragma unroll
        for (int i = threadIdx.x; i < K_DIM / 4; i += RD_THREADS) {
            float4 a = xv[i];
            float4 b = wv[i];
            acc += a.x * b.x + a.y * b.y + a.z * b.z + a.w * b.w;
        }

#pragma unroll
        for (int off = 16; off > 0; off >>= 1)
            acc += __shfl_down_sync(0xFFFFFFFFu, acc, off);

        if ((threadIdx.x & 31) == 0) warp_sums[rr][threadIdx.x >> 5] = acc;
    }

    __syncthreads();

    // First ROWS_PER_BLOCK warps each finish one row.
    const int wid = threadIdx.x >> 5;
    const int lid = threadIdx.x & 31;
    if (wid < ROWS_PER_BLOCK) {
        float v = (lid < RD_THREADS / 32) ? warp_sums[wid][lid] : 0.0f;
#pragma unroll
        for (int off = 4; off > 0; off >>= 1)
            v += __shfl_down_sync(0xFFFFFFFFu, v, off);
        if (lid == 0) y[m0 + wid] = 0.75f * v;
    }
}

// ---------------------------------------------------------------------------
// Launch
// ---------------------------------------------------------------------------
extern "C" void kernel_launch(void* const* d_in, const int* in_sizes, int n_in,
                              void* d_out, int out_size) {
    const float* x = (const float*)d_in[0];      // [M, K]
    const float* W = (const float*)d_in[1];      // [N, K]
    float* y = (float*)d_out;                    // [M, 1]

    zero_wcs_kernel<<<(K_DIM + 255) / 256, 256>>>();

    dim3 cs_grid(K_DIM / 4 / CS_THREADS, ROW_SPLITS);  // (8, 128)
    colsum_kernel<<<cs_grid, CS_THREADS>>>(W);

    rowdot_kernel<<<M_DIM / ROWS_PER_BLOCK, RD_THREADS>>>(x, y);
}

// round 3
// speedup vs baseline: 1.0140x; 1.0140x over previous
#include <cuda_runtime.h>
#include <cuda_bf16.h>

// y = 0.75 * x @ colsum(W)
// x: [M,K] fp32 row-major, W: [N,K] fp32 row-major, out: [M,1] fp32
// M = K = N = 8192.

#define M_DIM 8192
#define K_DIM 8192
#define N_DIM 8192

// Scratch: column sums of W. __device__ global (no allocations allowed).
__device__ float g_wcs[K_DIM];

// ---------------------------------------------------------------------------
// Kernel 1: column-sum of W.
// Grid: (K/4/256, ROW_SPLITS). Each thread owns one float4 column group and
// accumulates ROWS_PER_SPLIT rows with 4 independent accumulators
// (structural MLP >= 4..16), then 4 atomicAdds into g_wcs.
// W is read once -> streaming loads (__ldcs) keep it from thrashing L2.
// ---------------------------------------------------------------------------
#define CS_THREADS 256
#define ROW_SPLITS 128
#define ROWS_PER_SPLIT (N_DIM / ROW_SPLITS)   // 64

__global__ __launch_bounds__(CS_THREADS)
void colsum_kernel(const float* __restrict__ W) {
    const int col4 = blockIdx.x * CS_THREADS + threadIdx.x;  // float4 index
    const int r0 = blockIdx.y * ROWS_PER_SPLIT;
    const float4* __restrict__ Wv = reinterpret_cast<const float4*>(W);
    const long long ld4 = K_DIM / 4;

    float4 a0 = make_float4(0.f, 0.f, 0.f, 0.f);
    float4 a1 = make_float4(0.f, 0.f, 0.f, 0.f);
    float4 a2 = make_float4(0.f, 0.f, 0.f, 0.f);
    float4 a3 = make_float4(0.f, 0.f, 0.f, 0.f);

#pragma unroll 4
    for (int r = 0; r < ROWS_PER_SPLIT; r += 4) {
        float4 v0 = __ldcs(&Wv[(long long)(r0 + r + 0) * ld4 + col4]);
        float4 v1 = __ldcs(&Wv[(long long)(r0 + r + 1) * ld4 + col4]);
        float4 v2 = __ldcs(&Wv[(long long)(r0 + r + 2) * ld4 + col4]);
        float4 v3 = __ldcs(&Wv[(long long)(r0 + r + 3) * ld4 + col4]);
        a0.x += v0.x; a0.y += v0.y; a0.z += v0.z; a0.w += v0.w;
        a1.x += v1.x; a1.y += v1.y; a1.z += v1.z; a1.w += v1.w;
        a2.x += v2.x; a2.y += v2.y; a2.z += v2.z; a2.w += v2.w;
        a3.x += v3.x; a3.y += v3.y; a3.z += v3.z; a3.w += v3.w;
    }

    float4 acc;
    acc.x = (a0.x + a1.x) + (a2.x + a3.x);
    acc.y = (a0.y + a1.y) + (a2.y + a3.y);
    acc.z = (a0.z + a1.z) + (a2.z + a3.z);
    acc.w = (a0.w + a1.w) + (a2.w + a3.w);

    float* dst = &g_wcs[col4 * 4];
    atomicAdd(dst + 0, acc.x);
    atomicAdd(dst + 1, acc.y);
    atomicAdd(dst + 2, acc.z);
    atomicAdd(dst + 3, acc.w);
}

// ---------------------------------------------------------------------------
// Kernel 2: per-row dot product against g_wcs (32 KB, L1/L2-resident).
// 2 rows per block, interleaved in one loop so each wcs load is shared by
// two independent FFMA chains. x is streamed once -> __ldcs.
// ---------------------------------------------------------------------------
#define RD_THREADS 256
#define ROWS_PER_BLOCK 2

__global__ __launch_bounds__(RD_THREADS)
void rowdot_kernel(const float* __restrict__ x, float* __restrict__ y) {
    const float4* __restrict__ wv = reinterpret_cast<const float4*>(g_wcs);
    __shared__ float warp_sums[ROWS_PER_BLOCK][RD_THREADS / 32];

    const int m0 = blockIdx.x * ROWS_PER_BLOCK;
    const float4* __restrict__ xv0 =
        reinterpret_cast<const float4*>(x + (long long)m0 * K_DIM);
    const float4* __restrict__ xv1 =
        reinterpret_cast<const float4*>(x + (long long)(m0 + 1) * K_DIM);

    float acc0 = 0.0f, acc1 = 0.0f;
    // K/4 = 2048 float4 per row; 256 threads -> 8 iterations each.
#pragma unroll
    for (int i = threadIdx.x; i < K_DIM / 4; i += RD_THREADS) {
        float4 b = __ldg(&wv[i]);
        float4 p = __ldcs(&xv0[i]);
        float4 q = __ldcs(&xv1[i]);
        acc0 += p.x * b.x + p.y * b.y + p.z * b.z + p.w * b.w;
        acc1 += q.x * b.x + q.y * b.y + q.z * b.z + q.w * b.w;
    }

#pragma unroll
    for (int off = 16; off > 0; off >>= 1) {
        acc0 += __shfl_down_sync(0xFFFFFFFFu, acc0, off);
        acc1 += __shfl_down_sync(0xFFFFFFFFu, acc1, off);
    }

    if ((threadIdx.x & 31) == 0) {
        warp_sums[0][threadIdx.x >> 5] = acc0;
        warp_sums[1][threadIdx.x >> 5] = acc1;
    }
    __syncthreads();

    // First ROWS_PER_BLOCK warps each finish one row (8 partials each).
    const int wid = threadIdx.x >> 5;
    const int lid = threadIdx.x & 31;
    if (wid < ROWS_PER_BLOCK) {
        float v = (lid < RD_THREADS / 32) ? warp_sums[wid][lid] : 0.0f;
#pragma unroll
        for (int off = 4; off > 0; off >>= 1)
            v += __shfl_down_sync(0xFFFFFFFFu, v, off);
        if (lid == 0) y[m0 + wid] = 0.75f * v;
    }
}

// ---------------------------------------------------------------------------
// Launch. g_wcs is zeroed via a memset node (capturable, cheaper than a
// kernel, and keeps ncu's skip-count landing on a real kernel).
// ---------------------------------------------------------------------------
extern "C" void kernel_launch(void* const* d_in, const int* in_sizes, int n_in,
                              void* d_out, int out_size) {
    const float* x = (const float*)d_in[0];      // [M, K]
    const float* W = (const float*)d_in[1];      // [N, K]
    float* y = (float*)d_out;                    // [M, 1]

    void* wcs_ptr = nullptr;
    cudaGetSymbolAddress(&wcs_ptr, g_wcs);
    cudaMemsetAsync(wcs_ptr, 0, K_DIM * sizeof(float));

    dim3 cs_grid(K_DIM / 4 / CS_THREADS, ROW_SPLITS);  // (8, 128)
    colsum_kernel<<<cs_grid, CS_THREADS>>>(W);

    rowdot_kernel<<<M_DIM / ROWS_PER_BLOCK, RD_THREADS>>>(x, y);
}

// round 4
// speedup vs baseline: 1.0667x; 1.0519x over previous
#include <cuda_runtime.h>
#include <cuda_bf16.h>

// y = 0.75 * x @ colsum(W)
// x: [M,K] fp32 row-major, W: [N,K] fp32 row-major, out: [M,1] fp32
// M = K = N = 8192.

#define M_DIM 8192
#define K_DIM 8192
#define N_DIM 8192

// Scratch: column sums of W. __device__ global (no allocations allowed).
__device__ float g_wcs[K_DIM];

// ---------------------------------------------------------------------------
// Kernel 1: column-sum of W.
// Grid: (K/4/256, ROW_SPLITS) = (8, 64). Each thread owns one float4 column
// group and accumulates 128 rows; loads batched 8-deep per iteration into 4
// independent accumulators (structural MLP >= 8). 4 atomicAdds per thread
// at the end (512K total, half of the previous version).
// ---------------------------------------------------------------------------
#define CS_THREADS 256
#define ROW_SPLITS 64
#define ROWS_PER_SPLIT (N_DIM / ROW_SPLITS)   // 128

__global__ __launch_bounds__(CS_THREADS)
void colsum_kernel(const float* __restrict__ W) {
    const int col4 = blockIdx.x * CS_THREADS + threadIdx.x;  // float4 index
    const int r0 = blockIdx.y * ROWS_PER_SPLIT;
    const float4* __restrict__ Wv = reinterpret_cast<const float4*>(W);
    const long long ld4 = K_DIM / 4;

    float4 a0 = make_float4(0.f, 0.f, 0.f, 0.f);
    float4 a1 = make_float4(0.f, 0.f, 0.f, 0.f);
    float4 a2 = make_float4(0.f, 0.f, 0.f, 0.f);
    float4 a3 = make_float4(0.f, 0.f, 0.f, 0.f);

    const float4* p = &Wv[(long long)r0 * ld4 + col4];

#pragma unroll 2
    for (int r = 0; r < ROWS_PER_SPLIT; r += 8) {
        float4 v0 = __ldcs(p + 0 * ld4);
        float4 v1 = __ldcs(p + 1 * ld4);
        float4 v2 = __ldcs(p + 2 * ld4);
        float4 v3 = __ldcs(p + 3 * ld4);
        float4 v4 = __ldcs(p + 4 * ld4);
        float4 v5 = __ldcs(p + 5 * ld4);
        float4 v6 = __ldcs(p + 6 * ld4);
        float4 v7 = __ldcs(p + 7 * ld4);
        p += 8 * ld4;
        a0.x += v0.x; a0.y += v0.y; a0.z += v0.z; a0.w += v0.w;
        a1.x += v1.x; a1.y += v1.y; a1.z += v1.z; a1.w += v1.w;
        a2.x += v2.x; a2.y += v2.y; a2.z += v2.z; a2.w += v2.w;
        a3.x += v3.x; a3.y += v3.y; a3.z += v3.z; a3.w += v3.w;
        a0.x += v4.x; a0.y += v4.y; a0.z += v4.z; a0.w += v4.w;
        a1.x += v5.x; a1.y += v5.y; a1.z += v5.z; a1.w += v5.w;
        a2.x += v6.x; a2.y += v6.y; a2.z += v6.z; a2.w += v6.w;
        a3.x += v7.x; a3.y += v7.y; a3.z += v7.z; a3.w += v7.w;
    }

    float4 acc;
    acc.x = (a0.x + a1.x) + (a2.x + a3.x);
    acc.y = (a0.y + a1.y) + (a2.y + a3.y);
    acc.z = (a0.z + a1.z) + (a2.z + a3.z);
    acc.w = (a0.w + a1.w) + (a2.w + a3.w);

    float* dst = &g_wcs[col4 * 4];
    atomicAdd(dst + 0, acc.x);
    atomicAdd(dst + 1, acc.y);
    atomicAdd(dst + 2, acc.z);
    atomicAdd(dst + 3, acc.w);
}

// ---------------------------------------------------------------------------
// Kernel 2: per-row dot product against g_wcs (32 KB, L1/L2-resident).
// 4 rows per block interleaved in one loop: each wcs load feeds 4 independent
// FFMA chains; 5 independent loads per iteration, 8 iterations.
// ---------------------------------------------------------------------------
#define RD_THREADS 256
#define ROWS_PER_BLOCK 4

__global__ __launch_bounds__(RD_THREADS)
void rowdot_kernel(const float* __restrict__ x, float* __restrict__ y) {
    const float4* __restrict__ wv = reinterpret_cast<const float4*>(g_wcs);
    __shared__ float warp_sums[ROWS_PER_BLOCK][RD_THREADS / 32];

    const int m0 = blockIdx.x * ROWS_PER_BLOCK;
    const float4* __restrict__ xv0 =
        reinterpret_cast<const float4*>(x + (long long)(m0 + 0) * K_DIM);
    const float4* __restrict__ xv1 =
        reinterpret_cast<const float4*>(x + (long long)(m0 + 1) * K_DIM);
    const float4* __restrict__ xv2 =
        reinterpret_cast<const float4*>(x + (long long)(m0 + 2) * K_DIM);
    const float4* __restrict__ xv3 =
        reinterpret_cast<const float4*>(x + (long long)(m0 + 3) * K_DIM);

    float acc0 = 0.f, acc1 = 0.f, acc2 = 0.f, acc3 = 0.f;
    // K/4 = 2048 float4 per row; 256 threads -> 8 iterations each.
#pragma unroll
    for (int i = threadIdx.x; i < K_DIM / 4; i += RD_THREADS) {
        float4 b = __ldg(&wv[i]);
        float4 p = __ldcs(&xv0[i]);
        float4 q = __ldcs(&xv1[i]);
        float4 r = __ldcs(&xv2[i]);
        float4 s = __ldcs(&xv3[i]);
        acc0 += p.x * b.x + p.y * b.y + p.z * b.z + p.w * b.w;
        acc1 += q.x * b.x + q.y * b.y + q.z * b.z + q.w * b.w;
        acc2 += r.x * b.x + r.y * b.y + r.z * b.z + r.w * b.w;
        acc3 += s.x * b.x + s.y * b.y + s.z * b.z + s.w * b.w;
    }

#pragma unroll
    for (int off = 16; off > 0; off >>= 1) {
        acc0 += __shfl_down_sync(0xFFFFFFFFu, acc0, off);
        acc1 += __shfl_down_sync(0xFFFFFFFFu, acc1, off);
        acc2 += __shfl_down_sync(0xFFFFFFFFu, acc2, off);
        acc3 += __shfl_down_sync(0xFFFFFFFFu, acc3, off);
    }

    if ((threadIdx.x & 31) == 0) {
        warp_sums[0][threadIdx.x >> 5] = acc0;
        warp_sums[1][threadIdx.x >> 5] = acc1;
        warp_sums[2][threadIdx.x >> 5] = acc2;
        warp_sums[3][threadIdx.x >> 5] = acc3;
    }
    __syncthreads();

    // First ROWS_PER_BLOCK warps each finish one row (8 partials each).
    const int wid = threadIdx.x >> 5;
    const int lid = threadIdx.x & 31;
    if (wid < ROWS_PER_BLOCK) {
        float v = (lid < RD_THREADS / 32) ? warp_sums[wid][lid] : 0.0f;
#pragma unroll
        for (int off = 4; off > 0; off >>= 1)
            v += __shfl_down_sync(0xFFFFFFFFu, v, off);
        if (lid == 0) y[m0 + wid] = 0.75f * v;
    }
}

// ---------------------------------------------------------------------------
// Launch. g_wcs zeroed via memset node (capturable, no kernel).
// ---------------------------------------------------------------------------
extern "C" void kernel_launch(void* const* d_in, const int* in_sizes, int n_in,
                              void* d_out, int out_size) {
    const float* x = (const float*)d_in[0];      // [M, K]
    const float* W = (const float*)d_in[1];      // [N, K]
    float* y = (float*)d_out;                    // [M, 1]

    void* wcs_ptr = nullptr;
    cudaGetSymbolAddress(&wcs_ptr, g_wcs);
    cudaMemsetAsync(wcs_ptr, 0, K_DIM * sizeof(float));

    dim3 cs_grid(K_DIM / 4 / CS_THREADS, ROW_SPLITS);  // (8, 64)
    colsum_kernel<<<cs_grid, CS_THREADS>>>(W);

    rowdot_kernel<<<M_DIM / ROWS_PER_BLOCK, RD_THREADS>>>(x, y);
}